// round 2
// baseline (speedup 1.0000x reference)
#include <cuda_runtime.h>
#include <cstdint>
#include <cmath>

// Problem constants
constexpr int Qn = 128;      // slices
constexpr int Sn = 128;      // slice length (K)
constexpr int Hn = 32;       // hidden (N)
constexpr int Cn = Qn * Sn;  // 16384 channels
constexpr int MT = 128;      // batch rows per CTA

// SMEM layout in floats. Stride 132 (=128+4): bank(r*132+c) = (4r+c) mod 32,
// conflict-free for the m16n8k8 fragment access pattern.
constexpr int AS = 132;                       // A row stride (floats)
constexpr int OFF_A  = 0;                     // A: [128][132]
constexpr int OFF_B  = OFF_A + MT * AS;       // B^T: [32][132] (n-major, k contiguous-ish)
constexpr int OFF_B1 = OFF_B + Hn * AS;       // b1[32]
constexpr int OFF_W2 = OFF_B1 + Hn;           // W2[32]
constexpr int OFF_B2 = OFF_W2 + Hn;           // b2
constexpr int SMEM_FLOATS = OFF_B2 + 4;
constexpr int SMEM_BYTES  = SMEM_FLOATS * 4;  // ~84.8 KB -> 2 CTAs/SM

static __device__ __forceinline__ uint32_t tf32rna(float f) {
    uint32_t r;
    asm("cvt.rna.tf32.f32 %0, %1;" : "=r"(r) : "f"(f));
    return r;
}

static __device__ __forceinline__ void mma_tf32(
    float& c0, float& c1, float& c2, float& c3,
    uint32_t a0, uint32_t a1, uint32_t a2, uint32_t a3,
    uint32_t b0, uint32_t b1)
{
    asm volatile(
        "mma.sync.aligned.m16n8k8.row.col.f32.tf32.tf32.f32 "
        "{%0,%1,%2,%3}, {%4,%5,%6,%7}, {%8,%9}, {%0,%1,%2,%3};"
        : "+f"(c0), "+f"(c1), "+f"(c2), "+f"(c3)
        : "r"(a0), "r"(a1), "r"(a2), "r"(a3), "r"(b0), "r"(b1));
}

__global__ void __launch_bounds__(128, 2) divenc_kernel(
    const float* __restrict__ x,   // [B, C]
    const float* __restrict__ W1,  // [Q, S, H]
    const float* __restrict__ b1,  // [Q, H]
    const float* __restrict__ W2,  // [Q, H]
    const float* __restrict__ b2,  // [Q]
    float* __restrict__ out)       // [B, Q]
{
    extern __shared__ float sm[];
    const int tid  = threadIdx.x;
    const int wid  = tid >> 5;
    const int lane = tid & 31;
    const int g    = lane >> 2;   // group id (row within fragment)
    const int t    = lane & 3;    // thread-in-quad (col within fragment)
    const int q  = blockIdx.x & (Qn - 1);
    const int mt = blockIdx.x >> 7;

    // ---- Stage A: x tile [128 rows x 128 K] -> smem (rna-converted to tf32) ----
    const float* xb = x + (size_t)(mt * MT) * Cn + (size_t)q * Sn;
    #pragma unroll 8
    for (int i = 0; i < 32; i++) {
        int idx = i * 128 + tid;      // 4096 float4s
        int r   = idx >> 5;           // batch row
        int c4  = idx & 31;           // 16B chunk along K
        float4 v = *reinterpret_cast<const float4*>(xb + (size_t)r * Cn + c4 * 4);
        float* d = sm + OFF_A + r * AS + c4 * 4;
        d[0] = __uint_as_float(tf32rna(v.x));
        d[1] = __uint_as_float(tf32rna(v.y));
        d[2] = __uint_as_float(tf32rna(v.z));
        d[3] = __uint_as_float(tf32rna(v.w));
    }

    // ---- Stage B: W1[q] transposed -> smem[n][k] ----
    const float* w1 = W1 + (size_t)q * Sn * Hn;
    #pragma unroll 8
    for (int i = 0; i < 32; i++) {
        int idx = i * 128 + tid;      // 4096 floats
        int k = idx >> 5;             // K index
        int n = idx & 31;             // H index
        sm[OFF_B + n * AS + k] = __uint_as_float(tf32rna(w1[idx]));
    }

    if (tid < Hn) {
        sm[OFF_B1 + tid] = b1[q * Hn + tid];
        sm[OFF_W2 + tid] = W2[q * Hn + tid];
    }
    if (tid == 0) sm[OFF_B2] = b2[q];
    __syncthreads();

    // ---- MMA mainloop: each warp does M=32 x N=32 x K=128 ----
    // 2 M-frags x 4 N-frags x 16 K-steps of m16n8k8 tf32.
    float c[2][4][4];
    #pragma unroll
    for (int mf = 0; mf < 2; mf++)
        #pragma unroll
        for (int nf = 0; nf < 4; nf++)
            #pragma unroll
            for (int e = 0; e < 4; e++) c[mf][nf][e] = 0.0f;

    const int mbase = wid * 32;
    const float* sA = sm + OFF_A;
    const float* sB = sm + OFF_B;

    #pragma unroll
    for (int ks = 0; ks < 16; ks++) {
        const int k0 = ks * 8;
        uint32_t a[2][4];
        #pragma unroll
        for (int mf = 0; mf < 2; mf++) {
            const float* ar = sA + (mbase + mf * 16 + g) * AS + k0 + t;
            a[mf][0] = __float_as_uint(ar[0]);
            a[mf][1] = __float_as_uint(ar[8 * AS]);
            a[mf][2] = __float_as_uint(ar[4]);
            a[mf][3] = __float_as_uint(ar[8 * AS + 4]);
        }
        uint32_t b[4][2];
        #pragma unroll
        for (int nf = 0; nf < 4; nf++) {
            const float* br = sB + (nf * 8 + g) * AS + k0 + t;
            b[nf][0] = __float_as_uint(br[0]);
            b[nf][1] = __float_as_uint(br[4]);
        }
        #pragma unroll
        for (int mf = 0; mf < 2; mf++)
            #pragma unroll
            for (int nf = 0; nf < 4; nf++)
                mma_tf32(c[mf][nf][0], c[mf][nf][1], c[mf][nf][2], c[mf][nf][3],
                         a[mf][0], a[mf][1], a[mf][2], a[mf][3],
                         b[nf][0], b[nf][1]);
    }

    // ---- Epilogue: +b1, ELU, dot W2, +b2, quad-reduce, store ----
    // Thread holds rows {mbase+mf*16+g, +8}, cols {nf*8 + 2t, 2t+1}.
    const float bias2 = sm[OFF_B2];
    #pragma unroll
    for (int mf = 0; mf < 2; mf++) {
        #pragma unroll
        for (int h = 0; h < 2; h++) {
            float partial = 0.0f;
            #pragma unroll
            for (int nf = 0; nf < 4; nf++) {
                #pragma unroll
                for (int e = 0; e < 2; e++) {
                    int col = nf * 8 + 2 * t + e;
                    float v = c[mf][nf][h * 2 + e] + sm[OFF_B1 + col];
                    v = (v > 0.0f) ? v : expm1f(v);
                    partial = fmaf(v, sm[OFF_W2 + col], partial);
                }
            }
            partial += __shfl_xor_sync(0xFFFFFFFFu, partial, 1);
            partial += __shfl_xor_sync(0xFFFFFFFFu, partial, 2);
            if (t == 0) {
                int m = mt * MT + mbase + mf * 16 + h * 8 + g;
                out[(size_t)m * Qn + q] = partial + bias2;
            }
        }
    }
}

extern "C" void kernel_launch(void* const* d_in, const int* in_sizes, int n_in,
                              void* d_out, int out_size) {
    const float* x  = (const float*)d_in[0];
    const float* W1 = (const float*)d_in[1];
    const float* b1 = (const float*)d_in[2];
    const float* W2 = (const float*)d_in[3];
    const float* b2 = (const float*)d_in[4];
    float* out = (float*)d_out;

    int B = in_sizes[0] / Cn;          // 2048
    int grid = (B / MT) * Qn;          // 2048 CTAs

    static bool configured = false;
    if (!configured) {
        cudaFuncSetAttribute(divenc_kernel,
                             cudaFuncAttributeMaxDynamicSharedMemorySize, SMEM_BYTES);
        configured = true;
    }
    divenc_kernel<<<grid, 128, SMEM_BYTES>>>(x, W1, b1, W2, b2, out);
}

// round 3
// speedup vs baseline: 1.7781x; 1.7781x over previous
#include <cuda_runtime.h>
#include <cstdint>

// Problem constants
constexpr int Qn = 128;      // slices
constexpr int Sn = 128;      // slice length (K)
constexpr int Hn = 32;       // hidden (N)
constexpr int Cn = Qn * Sn;  // 16384 channels
constexpr int MT = 64;       // batch rows per tile

// SMEM layout in floats, double buffered.
constexpr int AS = 132;                    // A row stride: bank(132r+k)=(4r+k)%32 -> conflict-free a-frags
constexpr int BS = 40;                     // B row stride: bank(40k+n)=(8k+n)%32 -> conflict-free b-frags
constexpr int OFF_A    = 0;                // A: [64][132]
constexpr int OFF_B    = OFF_A + MT * AS;  // B: [128][40] (k-major, n contiguous)
constexpr int OFF_BIAS = OFF_B + Sn * BS;  // b1[32], W2[32], b2[1]
constexpr int STAGE = 13648;               // floats per stage (16B aligned)
constexpr int SMEM_BYTES = 2 * STAGE * 4;  // 109184 B -> 2 CTAs/SM
constexpr int GRID = 296;                  // 2 CTAs x 148 SMs, all resident

static __device__ __forceinline__ uint32_t smem_u32(const void* p) {
    uint32_t a;
    asm("{ .reg .u64 t; cvta.to.shared.u64 t, %1; cvt.u32.u64 %0, t; }" : "=r"(a) : "l"(p));
    return a;
}

static __device__ __forceinline__ uint32_t tf32rna(float f) {
    uint32_t r;
    asm("cvt.rna.tf32.f32 %0, %1;" : "=r"(r) : "f"(f));
    return r;
}

#define CP16(dst, src) \
    asm volatile("cp.async.cg.shared.global [%0], [%1], 16;" :: "r"(dst), "l"(src))
#define CP4(dst, src) \
    asm volatile("cp.async.ca.shared.global [%0], [%1], 4;" :: "r"(dst), "l"(src))

static __device__ __forceinline__ void mma_tf32(
    float& c0, float& c1, float& c2, float& c3,
    uint32_t a0, uint32_t a1, uint32_t a2, uint32_t a3,
    uint32_t b0, uint32_t b1)
{
    asm volatile(
        "mma.sync.aligned.m16n8k8.row.col.f32.tf32.tf32.f32 "
        "{%0,%1,%2,%3}, {%4,%5,%6,%7}, {%8,%9}, {%0,%1,%2,%3};"
        : "+f"(c0), "+f"(c1), "+f"(c2), "+f"(c3)
        : "r"(a0), "r"(a1), "r"(a2), "r"(a3), "r"(b0), "r"(b1));
}

// Prefetch tile (mt,q) into stage s via cp.async (one commit group).
static __device__ __forceinline__ void prefetch_tile(
    uint32_t sb, int s, int tile, int tid,
    const float* __restrict__ x, const float* __restrict__ W1,
    const float* __restrict__ b1, const float* __restrict__ W2,
    const float* __restrict__ b2)
{
    const int q  = tile & (Qn - 1);
    const int mt = tile >> 7;
    const uint32_t base = sb + (uint32_t)s * (STAGE * 4);

    // A: x tile [64 rows x 128 K] -> [64][132] floats
    const float* xb = x + (size_t)(mt * MT) * Cn + (size_t)q * Sn;
    const uint32_t dA = base + OFF_A * 4;
    #pragma unroll
    for (int i = 0; i < 16; i++) {
        int idx = i * 128 + tid;       // 2048 16B chunks
        int r   = idx >> 5;
        int c4  = idx & 31;
        CP16(dA + r * (AS * 4) + c4 * 16, xb + (size_t)r * Cn + c4 * 4);
    }

    // B: W1[q] [128 k x 32 n] raw -> [128][40] floats
    const float* w1 = W1 + (size_t)q * Sn * Hn;
    const uint32_t dB = base + OFF_B * 4;
    #pragma unroll
    for (int i = 0; i < 8; i++) {
        int idx = i * 128 + tid;       // 1024 16B chunks
        int k  = idx >> 3;
        int h4 = idx & 7;
        CP16(dB + k * (BS * 4) + h4 * 16, w1 + k * Hn + h4 * 4);
    }

    // Biases: b1[32], W2[32], b2[1]
    const uint32_t dBias = base + OFF_BIAS * 4;
    if (tid < 16) {
        const float* src = (tid < 8) ? (b1 + q * Hn + tid * 4)
                                     : (W2 + q * Hn + (tid - 8) * 4);
        CP16(dBias + tid * 16, src);
    } else if (tid == 16) {
        CP4(dBias + 64 * 4, b2 + q);
    }
    asm volatile("cp.async.commit_group;" ::: "memory");
}

__global__ void __launch_bounds__(128, 2) divenc_kernel(
    const float* __restrict__ x,   // [B, C]
    const float* __restrict__ W1,  // [Q, S, H]
    const float* __restrict__ b1,  // [Q, H]
    const float* __restrict__ W2,  // [Q, H]
    const float* __restrict__ b2,  // [Q]
    float* __restrict__ out,       // [B, Q]
    int ntiles)
{
    extern __shared__ float sm[];
    const uint32_t sb = smem_u32(sm);
    const int tid  = threadIdx.x;
    const int wid  = tid >> 5;
    const int lane = tid & 31;
    const int g    = lane >> 2;    // fragment row
    const int t    = lane & 3;     // fragment col quad

    int tile = blockIdx.x;
    if (tile >= ntiles) return;

    // Prologue prefetch
    prefetch_tile(sb, 0, tile, tid, x, W1, b1, W2, b2);

    int s = 0;
    for (; tile < ntiles; tile += GRID) {
        const int tn = tile + GRID;
        if (tn < ntiles) {
            prefetch_tile(sb, s ^ 1, tn, tid, x, W1, b1, W2, b2);
            asm volatile("cp.async.wait_group 1;" ::: "memory");
        } else {
            asm volatile("cp.async.wait_group 0;" ::: "memory");
        }
        __syncthreads();

        const float* sA = sm + s * STAGE + OFF_A;
        const float* sB = sm + s * STAGE + OFF_B;
        const float* sBias = sm + s * STAGE + OFF_BIAS;

        // ---- MMA: warp computes M=16 x N=32 x K=128 ----
        float c[4][4];
        #pragma unroll
        for (int nf = 0; nf < 4; nf++)
            #pragma unroll
            for (int e = 0; e < 4; e++) c[nf][e] = 0.0f;

        const int mbase = wid * 16;
        const float* arow0 = sA + (mbase + g) * AS + t;
        const float* arow1 = arow0 + 8 * AS;
        const float* brow  = sB + t * BS;          // + k0*BS + n

        #pragma unroll
        for (int ks = 0; ks < 16; ks++) {
            const int k0 = ks * 8;
            uint32_t a0 = tf32rna(arow0[k0]);
            uint32_t a1 = tf32rna(arow1[k0]);
            uint32_t a2 = tf32rna(arow0[k0 + 4]);
            uint32_t a3 = tf32rna(arow1[k0 + 4]);
            #pragma unroll
            for (int nf = 0; nf < 4; nf++) {
                const int n = nf * 8 + g;
                uint32_t b0r = __float_as_uint(brow[k0 * BS + n]);
                uint32_t b1r = __float_as_uint(brow[(k0 + 4) * BS + n]);
                mma_tf32(c[nf][0], c[nf][1], c[nf][2], c[nf][3],
                         a0, a1, a2, a3, b0r, b1r);
            }
        }

        // ---- Epilogue: +b1, ELU, dot W2, +b2, quad-reduce, store ----
        const int q  = tile & (Qn - 1);
        const int mt = tile >> 7;
        const float bias2 = sBias[64];
        float pA = 0.0f, pB = 0.0f;   // rows mbase+g, mbase+g+8
        #pragma unroll
        for (int nf = 0; nf < 4; nf++) {
            #pragma unroll
            for (int e = 0; e < 2; e++) {
                const int col = nf * 8 + 2 * t + e;
                const float w2c = sBias[32 + col];
                const float b1c = sBias[col];
                float vA = c[nf][e] + b1c;
                float vB = c[nf][2 + e] + b1c;
                vA = (vA > 0.0f) ? vA : (__expf(fminf(vA, 0.0f)) - 1.0f);
                vB = (vB > 0.0f) ? vB : (__expf(fminf(vB, 0.0f)) - 1.0f);
                pA = fmaf(vA, w2c, pA);
                pB = fmaf(vB, w2c, pB);
            }
        }
        pA += __shfl_xor_sync(0xFFFFFFFFu, pA, 1);
        pA += __shfl_xor_sync(0xFFFFFFFFu, pA, 2);
        pB += __shfl_xor_sync(0xFFFFFFFFu, pB, 1);
        pB += __shfl_xor_sync(0xFFFFFFFFu, pB, 2);
        if (t == 0) {
            const int m = mt * MT + mbase + g;
            out[(size_t)m * Qn + q]       = pA + bias2;
            out[(size_t)(m + 8) * Qn + q] = pB + bias2;
        }
        __syncthreads();   // protect stage s before it is overwritten at tile+2
        s ^= 1;
    }
}

extern "C" void kernel_launch(void* const* d_in, const int* in_sizes, int n_in,
                              void* d_out, int out_size) {
    const float* x  = (const float*)d_in[0];
    const float* W1 = (const float*)d_in[1];
    const float* b1 = (const float*)d_in[2];
    const float* W2 = (const float*)d_in[3];
    const float* b2 = (const float*)d_in[4];
    float* out = (float*)d_out;

    const int B = in_sizes[0] / Cn;            // 2048
    const int ntiles = (B / MT) * Qn;          // 4096

    static bool configured = false;
    if (!configured) {
        cudaFuncSetAttribute(divenc_kernel,
                             cudaFuncAttributeMaxDynamicSharedMemorySize, SMEM_BYTES);
        configured = true;
    }
    divenc_kernel<<<GRID, 128, SMEM_BYTES>>>(x, W1, b1, W2, b2, out, ntiles);
}